// round 9
// baseline (speedup 1.0000x reference)
#include <cuda_runtime.h>
#include <cuda_fp16.h>

// Problem constants (from reference)
#define NV 100000      // vertices
#define TT 128         // temporal depth
#define NE_MAX 1600000 // edges
#define MAXDEG 64      // padded segment capacity; deg ~ Poisson(16), P(>=64) ~ 2e-18/node

// ---------------- static device scratch (allocation-free) ----------------
__device__ __half g_hbuf[2][(size_t)NV * TT];     // ping-pong fp16 feature buffers (2 x 25.6MB)
__device__ int    g_deg[NV];
__device__ int    g_srcs[(size_t)NV * MAXDEG];    // padded segments; stores src*16 (uint4-row units)

// ---------------- helpers ----------------
__device__ __forceinline__ uint2 f4h2(float4 v) {
    __half2 a = __floats2half2_rn(v.x, v.y);
    __half2 b = __floats2half2_rn(v.z, v.w);
    uint2 r;
    r.x = *(unsigned*)&a;
    r.y = *(unsigned*)&b;
    return r;
}

// ---------------- input conversion fp32 -> fp16 (+ fused zeroing + out-bias init) ----------------
__global__ void k_cvt(const float4* __restrict__ x,
                      const float* __restrict__ bo, float* __restrict__ out) {
    int i = blockIdx.x * 256 + threadIdx.x; // NV*TT/4 = 3.2M
    ((uint2*)g_hbuf[0])[i] = f4h2(x[i]);
    if (i < NV) g_deg[i] = 0;
    if (i < TT * 3) out[i] = __ldg(bo + (i % 3)); // out is 0xAA-poisoned; init with bias
}

// ---------------- single-pass padded-CSR build ----------------
// The histogram atomic's return value IS the slot within dst's fixed-stride
// segment. No offsets, no rank array, no scatter pass.
__global__ void k_build(const int* __restrict__ src, const int* __restrict__ dst, int E) {
    int i = (blockIdx.x * 256 + threadIdx.x) * 4;
    if (i + 4 <= E) {
        int d0 = dst[i], d1 = dst[i + 1], d2 = dst[i + 2], d3 = dst[i + 3];
        int s0 = src[i], s1 = src[i + 1], s2 = src[i + 2], s3 = src[i + 3];
        int r0 = atomicAdd(&g_deg[d0], 1);
        int r1 = atomicAdd(&g_deg[d1], 1);
        int r2 = atomicAdd(&g_deg[d2], 1);
        int r3 = atomicAdd(&g_deg[d3], 1);
        if (r0 < MAXDEG) g_srcs[d0 * MAXDEG + r0] = s0 * 16; // premultiplied: uint4-row units
        if (r1 < MAXDEG) g_srcs[d1 * MAXDEG + r1] = s1 * 16;
        if (r2 < MAXDEG) g_srcs[d2 * MAXDEG + r2] = s2 * 16;
        if (r3 < MAXDEG) g_srcs[d3 * MAXDEG + r3] = s3 * 16;
    } else {
        for (; i < E; ++i) {
            int r = atomicAdd(&g_deg[dst[i]], 1);
            if (r < MAXDEG) g_srcs[dst[i] * MAXDEG + r] = src[i] * 16;
        }
    }
}

// ---------------- fused layer: mean-aggregate -> conv1d(K=9) -> relu ----------------
// conv and mean-agg commute exactly (linear; bias survives the mean).
// HALF-WARP per node: 16 lanes, each lane owns 8 consecutive t (one uint4 = 8 fp16).
// LDG.128 gathers; indices fetched 4-at-a-time via int4 (one LDG.128 vs 4 scalar).
// 8-edge fp16 tree (<=3 fp16 adds per value) then ONE convert + fp32 accumulate.
__global__ void __launch_bounds__(256) k_layer(
    int in_sel, int out_sel,
    const float* __restrict__ cw, const float* __restrict__ cb)
{
    const uint4* __restrict__ xin = (const uint4*)g_hbuf[in_sel];
    uint4* __restrict__ xout = (uint4*)g_hbuf[out_sel];

    int lane  = threadIdx.x & 31;
    int slane = lane & 15;
    int n = blockIdx.x * 16 + ((threadIdx.x >> 5) << 1) + (lane >> 4);

    float w[9];
    #pragma unroll
    for (int k = 0; k < 9; k++) w[k] = __ldg(cw + k);
    float bias = __ldg(cb);

    unsigned rbase = (unsigned)n * 16u + (unsigned)slane;

    float acc[8];
    { // self loop (exact convert)
        uint4 p = xin[rbase];
        const __half2* h = (const __half2*)&p;
        #pragma unroll
        for (int q = 0; q < 4; q++) {
            float2 f = __half22float2(h[q]);
            acc[2 * q] = f.x; acc[2 * q + 1] = f.y;
        }
    }

    int deg = g_deg[n];
    if (deg > MAXDEG) deg = MAXDEG; // paranoia; statistically unreachable
    const int* __restrict__ seg = g_srcs + n * MAXDEG; // 256B-aligned
    float inv = 1.0f / (float)(deg + 1); // mean incl. self loop

    int j = 0;
    for (; j + 8 <= deg; j += 8) {
        int4 ia = *(const int4*)(seg + j);
        uint4 p0 = xin[(unsigned)ia.x + slane];
        uint4 p1 = xin[(unsigned)ia.y + slane];
        uint4 p2 = xin[(unsigned)ia.z + slane];
        uint4 p3 = xin[(unsigned)ia.w + slane];
        __half2 t[4];
        {
            const __half2* h0 = (const __half2*)&p0;
            const __half2* h1 = (const __half2*)&p1;
            const __half2* h2 = (const __half2*)&p2;
            const __half2* h3 = (const __half2*)&p3;
            #pragma unroll
            for (int q = 0; q < 4; q++)
                t[q] = __hadd2(__hadd2(h0[q], h1[q]), __hadd2(h2[q], h3[q]));
        }
        int4 ib = *(const int4*)(seg + j + 4);
        uint4 p4 = xin[(unsigned)ib.x + slane];
        uint4 p5 = xin[(unsigned)ib.y + slane];
        uint4 p6 = xin[(unsigned)ib.z + slane];
        uint4 p7 = xin[(unsigned)ib.w + slane];
        {
            const __half2* h4 = (const __half2*)&p4;
            const __half2* h5 = (const __half2*)&p5;
            const __half2* h6 = (const __half2*)&p6;
            const __half2* h7 = (const __half2*)&p7;
            #pragma unroll
            for (int q = 0; q < 4; q++) {
                __half2 u = __hadd2(__hadd2(h4[q], h5[q]), __hadd2(h6[q], h7[q]));
                float2 f = __half22float2(__hadd2(t[q], u));
                acc[2 * q] += f.x;
                acc[2 * q + 1] += f.y;
            }
        }
    }
    if (j + 4 <= deg) {
        int4 ia = *(const int4*)(seg + j);
        uint4 p0 = xin[(unsigned)ia.x + slane];
        uint4 p1 = xin[(unsigned)ia.y + slane];
        uint4 p2 = xin[(unsigned)ia.z + slane];
        uint4 p3 = xin[(unsigned)ia.w + slane];
        const __half2* h0 = (const __half2*)&p0;
        const __half2* h1 = (const __half2*)&p1;
        const __half2* h2 = (const __half2*)&p2;
        const __half2* h3 = (const __half2*)&p3;
        #pragma unroll
        for (int q = 0; q < 4; q++) {
            __half2 s = __hadd2(__hadd2(h0[q], h1[q]), __hadd2(h2[q], h3[q]));
            float2 f = __half22float2(s);
            acc[2 * q] += f.x;
            acc[2 * q + 1] += f.y;
        }
        j += 4;
    }
    for (; j < deg; ++j) { // tail <=3 edges: exact converts
        uint4 p = xin[(unsigned)seg[j] + slane];
        const __half2* h = (const __half2*)&p;
        #pragma unroll
        for (int q = 0; q < 4; q++) {
            float2 f = __half22float2(h[q]);
            acc[2 * q] += f.x; acc[2 * q + 1] += f.y;
        }
    }

    #pragma unroll
    for (int q = 0; q < 8; q++) acc[q] *= inv;

    // conv halo via width-16 shuffles
    float vv[16];
    #pragma unroll
    for (int q = 0; q < 8; q++) vv[4 + q] = acc[q];
    #pragma unroll
    for (int q = 0; q < 4; q++)
        vv[q] = __shfl_up_sync(0xffffffffu, acc[4 + q], 1, 16);
    #pragma unroll
    for (int q = 0; q < 4; q++)
        vv[12 + q] = __shfl_down_sync(0xffffffffu, acc[q], 1, 16);
    if (slane == 0)  { vv[0] = 0.f; vv[1] = 0.f; vv[2] = 0.f; vv[3] = 0.f; }
    if (slane == 15) { vv[12] = 0.f; vv[13] = 0.f; vv[14] = 0.f; vv[15] = 0.f; }

    float res[8];
    #pragma unroll
    for (int i = 0; i < 8; i++) {
        float o = bias;
        #pragma unroll
        for (int k = 0; k < 9; k++) o = fmaf(vv[i + k], w[k], o); // cross-correlation
        res[i] = fmaxf(o, 0.0f);
    }

    uint4 outp;
    unsigned* op = (unsigned*)&outp;
    #pragma unroll
    for (int q = 0; q < 4; q++) {
        __half2 hh = __floats2half2_rn(res[2 * q], res[2 * q + 1]);
        op[q] = *(unsigned*)&hh;
    }
    xout[rbase] = outp;
}

// ---------------- final projection ----------------
// x.reshape(T,N) on row-major [N,T] is a flat reinterpretation:
// out[t,c] = b[c] + sum_n hflat[t*N+n] * W[c*N+n]; both contiguous in n.
#define TTILE 8
#define NCHF 8
__global__ void __launch_bounds__(512) k_final(
    const float* __restrict__ W, float* __restrict__ out)
{
    const __half* __restrict__ h = g_hbuf[1];
    int t0 = blockIdx.x * TTILE;
    const int nper = NV / NCHF; // 12500
    int n0 = blockIdx.y * nper;

    float acc[TTILE][3];
    #pragma unroll
    for (int t = 0; t < TTILE; t++)
        #pragma unroll
        for (int c = 0; c < 3; c++) acc[t][c] = 0.f;

    for (int n = n0 + threadIdx.x; n < n0 + nper; n += 512) {
        float w0 = __ldg(W + n);
        float w1 = __ldg(W + NV + n);
        float w2 = __ldg(W + 2 * NV + n);
        #pragma unroll
        for (int t = 0; t < TTILE; t++) {
            float v = __half2float(h[(size_t)(t0 + t) * NV + n]);
            acc[t][0] = fmaf(v, w0, acc[t][0]);
            acc[t][1] = fmaf(v, w1, acc[t][1]);
            acc[t][2] = fmaf(v, w2, acc[t][2]);
        }
    }

    #pragma unroll
    for (int t = 0; t < TTILE; t++)
        #pragma unroll
        for (int c = 0; c < 3; c++)
            #pragma unroll
            for (int o = 16; o; o >>= 1)
                acc[t][c] += __shfl_down_sync(0xffffffffu, acc[t][c], o);

    __shared__ float sh[16][TTILE][3];
    int lane = threadIdx.x & 31, wid = threadIdx.x >> 5;
    if (lane == 0)
        #pragma unroll
        for (int t = 0; t < TTILE; t++)
            #pragma unroll
            for (int c = 0; c < 3; c++) sh[wid][t][c] = acc[t][c];
    __syncthreads();
    // 24 outputs per block: lanes 0..23 of warp 0
    if (wid == 0 && lane < TTILE * 3) {
        int t = lane / 3, c = lane % 3;
        float s = 0.f;
        #pragma unroll
        for (int wgi = 0; wgi < 16; wgi++) s += sh[wgi][t][c];
        atomicAdd(&out[(t0 + t) * 3 + c], s);
    }
}

// ---------------- launch ----------------
extern "C" void kernel_launch(void* const* d_in, const int* in_sizes, int n_in,
                              void* d_out, int out_size)
{
    const float* x  = (const float*)d_in[0];
    const int*   ei = (const int*)d_in[1];
    const float* cw = (const float*)d_in[2]; // [L,1,1,K]
    const float* cb = (const float*)d_in[3]; // [L,1]
    const float* Wo = (const float*)d_in[4]; // [3,N]
    const float* bo = (const float*)d_in[5]; // [3]
    float* out = (float*)d_out;

    int E = in_sizes[1] / 2;
    const int* src = ei;
    const int* dst = ei + E;

    // input fp32 -> fp16 (+ zero deg, init out with bias)
    k_cvt<<<NV * TT / 4 / 256, 256>>>((const float4*)x, bo, out);

    // single-pass padded-CSR build (one atomic per edge, store fused)
    int eb = (E / 4 + 255) / 256 + 1;
    k_build<<<eb, 256>>>(src, dst, E);

    // 3 fused layers: agg -> conv -> relu, ping-pong fp16 buffers
    k_layer<<<NV / 16, 256>>>(0, 1, cw + 0, cb + 0);
    k_layer<<<NV / 16, 256>>>(1, 0, cw + 9, cb + 1);
    k_layer<<<NV / 16, 256>>>(0, 1, cw + 18, cb + 2);

    // final [T,3] projection
    k_final<<<dim3(TT / TTILE, NCHF), 512>>>(Wo, out);
}

// round 10
// speedup vs baseline: 1.0641x; 1.0641x over previous
#include <cuda_runtime.h>
#include <cuda_fp16.h>

// Problem constants (from reference)
#define NV 100000      // vertices
#define TT 128         // temporal depth
#define NE_MAX 1600000 // edges
#define MAXDEG 64      // padded segment capacity; deg ~ Poisson(16), P(>=64) ~ 2e-18/node

// ---------------- static device scratch (allocation-free) ----------------
__device__ __half g_hbuf[2][(size_t)NV * TT];     // ping-pong fp16 feature buffers (2 x 25.6MB)
__device__ int    g_deg[NV];
__device__ int    g_srcs[(size_t)NV * MAXDEG];    // padded segments; stores src*16 (uint4-row units)

// ---------------- helpers ----------------
__device__ __forceinline__ uint2 f4h2(float4 v) {
    __half2 a = __floats2half2_rn(v.x, v.y);
    __half2 b = __floats2half2_rn(v.z, v.w);
    uint2 r;
    r.x = *(unsigned*)&a;
    r.y = *(unsigned*)&b;
    return r;
}

// ---------------- input conversion fp32 -> fp16 (+ fused zeroing + out-bias init) ----------------
__global__ void k_cvt(const float4* __restrict__ x,
                      const float* __restrict__ bo, float* __restrict__ out) {
    int i = blockIdx.x * 256 + threadIdx.x; // NV*TT/4 = 3.2M
    ((uint2*)g_hbuf[0])[i] = f4h2(x[i]);
    if (i < NV) g_deg[i] = 0;
    if (i < TT * 3) out[i] = __ldg(bo + (i % 3)); // out is 0xAA-poisoned; init with bias
}

// ---------------- single-pass padded-CSR build ----------------
// The histogram atomic's return value IS the slot within dst's fixed-stride
// segment. No offsets, no rank array, no scatter pass.
__global__ void k_build(const int* __restrict__ src, const int* __restrict__ dst, int E) {
    int i = (blockIdx.x * 256 + threadIdx.x) * 4;
    if (i + 4 <= E) {
        int d0 = dst[i], d1 = dst[i + 1], d2 = dst[i + 2], d3 = dst[i + 3];
        int s0 = src[i], s1 = src[i + 1], s2 = src[i + 2], s3 = src[i + 3];
        int r0 = atomicAdd(&g_deg[d0], 1);
        int r1 = atomicAdd(&g_deg[d1], 1);
        int r2 = atomicAdd(&g_deg[d2], 1);
        int r3 = atomicAdd(&g_deg[d3], 1);
        if (r0 < MAXDEG) g_srcs[d0 * MAXDEG + r0] = s0 * 16; // premultiplied: uint4-row units
        if (r1 < MAXDEG) g_srcs[d1 * MAXDEG + r1] = s1 * 16;
        if (r2 < MAXDEG) g_srcs[d2 * MAXDEG + r2] = s2 * 16;
        if (r3 < MAXDEG) g_srcs[d3 * MAXDEG + r3] = s3 * 16;
    } else {
        for (; i < E; ++i) {
            int r = atomicAdd(&g_deg[dst[i]], 1);
            if (r < MAXDEG) g_srcs[dst[i] * MAXDEG + r] = src[i] * 16;
        }
    }
}

// ---------------- fused layer: mean-aggregate -> conv1d(K=9) -> relu ----------------
// conv and mean-agg commute exactly (linear; bias survives the mean).
// HALF-WARP per node: 16 lanes, each lane owns 8 consecutive t (one uint4 = 8 fp16).
// R8-proven body (4-edge fp16 tree groups, <=4 gathers in flight, 32 regs, occ 82%)
// + int4 index fetch (one LDG.128 for 4 indices). 8-edge trees regressed twice
// (R4, R9): register pressure kills occupancy; do not revisit.
__global__ void __launch_bounds__(256) k_layer(
    int in_sel, int out_sel,
    const float* __restrict__ cw, const float* __restrict__ cb)
{
    const uint4* __restrict__ xin = (const uint4*)g_hbuf[in_sel];
    uint4* __restrict__ xout = (uint4*)g_hbuf[out_sel];

    int lane  = threadIdx.x & 31;
    int slane = lane & 15;
    int n = blockIdx.x * 16 + ((threadIdx.x >> 5) << 1) + (lane >> 4);

    float w[9];
    #pragma unroll
    for (int k = 0; k < 9; k++) w[k] = __ldg(cw + k);
    float bias = __ldg(cb);

    unsigned rbase = (unsigned)n * 16u + (unsigned)slane;

    float acc[8];
    { // self loop (exact convert)
        uint4 p = xin[rbase];
        const __half2* h = (const __half2*)&p;
        #pragma unroll
        for (int q = 0; q < 4; q++) {
            float2 f = __half22float2(h[q]);
            acc[2 * q] = f.x; acc[2 * q + 1] = f.y;
        }
    }

    int deg = g_deg[n];
    if (deg > MAXDEG) deg = MAXDEG; // paranoia; statistically unreachable
    const int* __restrict__ seg = g_srcs + n * MAXDEG; // 256B-aligned
    float inv = 1.0f / (float)(deg + 1); // mean incl. self loop

    int j = 0;
    for (; j + 4 <= deg; j += 4) {
        int4 ia = *(const int4*)(seg + j); // 4 indices in one LDG.128
        uint4 p0 = xin[(unsigned)ia.x + slane];
        uint4 p1 = xin[(unsigned)ia.y + slane];
        uint4 p2 = xin[(unsigned)ia.z + slane];
        uint4 p3 = xin[(unsigned)ia.w + slane];
        const __half2* h0 = (const __half2*)&p0;
        const __half2* h1 = (const __half2*)&p1;
        const __half2* h2 = (const __half2*)&p2;
        const __half2* h3 = (const __half2*)&p3;
        #pragma unroll
        for (int q = 0; q < 4; q++) {
            __half2 a01 = __hadd2(h0[q], h1[q]);      // fp16 tree: 2-level
            __half2 a23 = __hadd2(h2[q], h3[q]);
            float2 f = __half22float2(__hadd2(a01, a23));
            acc[2 * q] += f.x;
            acc[2 * q + 1] += f.y;
        }
    }
    for (; j < deg; ++j) { // tail <=3 edges: exact converts
        uint4 p = xin[(unsigned)seg[j] + slane];
        const __half2* h = (const __half2*)&p;
        #pragma unroll
        for (int q = 0; q < 4; q++) {
            float2 f = __half22float2(h[q]);
            acc[2 * q] += f.x; acc[2 * q + 1] += f.y;
        }
    }

    #pragma unroll
    for (int q = 0; q < 8; q++) acc[q] *= inv;

    // conv halo via width-16 shuffles
    float vv[16];
    #pragma unroll
    for (int q = 0; q < 8; q++) vv[4 + q] = acc[q];
    #pragma unroll
    for (int q = 0; q < 4; q++)
        vv[q] = __shfl_up_sync(0xffffffffu, acc[4 + q], 1, 16);
    #pragma unroll
    for (int q = 0; q < 4; q++)
        vv[12 + q] = __shfl_down_sync(0xffffffffu, acc[q], 1, 16);
    if (slane == 0)  { vv[0] = 0.f; vv[1] = 0.f; vv[2] = 0.f; vv[3] = 0.f; }
    if (slane == 15) { vv[12] = 0.f; vv[13] = 0.f; vv[14] = 0.f; vv[15] = 0.f; }

    float res[8];
    #pragma unroll
    for (int i = 0; i < 8; i++) {
        float o = bias;
        #pragma unroll
        for (int k = 0; k < 9; k++) o = fmaf(vv[i + k], w[k], o); // cross-correlation
        res[i] = fmaxf(o, 0.0f);
    }

    uint4 outp;
    unsigned* op = (unsigned*)&outp;
    #pragma unroll
    for (int q = 0; q < 4; q++) {
        __half2 hh = __floats2half2_rn(res[2 * q], res[2 * q + 1]);
        op[q] = *(unsigned*)&hh;
    }
    xout[rbase] = outp;
}

// ---------------- final projection ----------------
// x.reshape(T,N) on row-major [N,T] is a flat reinterpretation:
// out[t,c] = b[c] + sum_n hflat[t*N+n] * W[c*N+n]; both contiguous in n.
#define TTILE 8
#define NCHF 8
__global__ void __launch_bounds__(512) k_final(
    const float* __restrict__ W, float* __restrict__ out)
{
    const __half* __restrict__ h = g_hbuf[1];
    int t0 = blockIdx.x * TTILE;
    const int nper = NV / NCHF; // 12500
    int n0 = blockIdx.y * nper;

    float acc[TTILE][3];
    #pragma unroll
    for (int t = 0; t < TTILE; t++)
        #pragma unroll
        for (int c = 0; c < 3; c++) acc[t][c] = 0.f;

    for (int n = n0 + threadIdx.x; n < n0 + nper; n += 512) {
        float w0 = __ldg(W + n);
        float w1 = __ldg(W + NV + n);
        float w2 = __ldg(W + 2 * NV + n);
        #pragma unroll
        for (int t = 0; t < TTILE; t++) {
            float v = __half2float(h[(size_t)(t0 + t) * NV + n]);
            acc[t][0] = fmaf(v, w0, acc[t][0]);
            acc[t][1] = fmaf(v, w1, acc[t][1]);
            acc[t][2] = fmaf(v, w2, acc[t][2]);
        }
    }

    #pragma unroll
    for (int t = 0; t < TTILE; t++)
        #pragma unroll
        for (int c = 0; c < 3; c++)
            #pragma unroll
            for (int o = 16; o; o >>= 1)
                acc[t][c] += __shfl_down_sync(0xffffffffu, acc[t][c], o);

    __shared__ float sh[16][TTILE][3];
    int lane = threadIdx.x & 31, wid = threadIdx.x >> 5;
    if (lane == 0)
        #pragma unroll
        for (int t = 0; t < TTILE; t++)
            #pragma unroll
            for (int c = 0; c < 3; c++) sh[wid][t][c] = acc[t][c];
    __syncthreads();
    // 24 outputs per block: lanes 0..23 of warp 0
    if (wid == 0 && lane < TTILE * 3) {
        int t = lane / 3, c = lane % 3;
        float s = 0.f;
        #pragma unroll
        for (int wgi = 0; wgi < 16; wgi++) s += sh[wgi][t][c];
        atomicAdd(&out[(t0 + t) * 3 + c], s);
    }
}

// ---------------- launch ----------------
extern "C" void kernel_launch(void* const* d_in, const int* in_sizes, int n_in,
                              void* d_out, int out_size)
{
    const float* x  = (const float*)d_in[0];
    const int*   ei = (const int*)d_in[1];
    const float* cw = (const float*)d_in[2]; // [L,1,1,K]
    const float* cb = (const float*)d_in[3]; // [L,1]
    const float* Wo = (const float*)d_in[4]; // [3,N]
    const float* bo = (const float*)d_in[5]; // [3]
    float* out = (float*)d_out;

    int E = in_sizes[1] / 2;
    const int* src = ei;
    const int* dst = ei + E;

    // input fp32 -> fp16 (+ zero deg, init out with bias)
    k_cvt<<<NV * TT / 4 / 256, 256>>>((const float4*)x, bo, out);

    // single-pass padded-CSR build (one atomic per edge, store fused)
    int eb = (E / 4 + 255) / 256 + 1;
    k_build<<<eb, 256>>>(src, dst, E);

    // 3 fused layers: agg -> conv -> relu, ping-pong fp16 buffers
    k_layer<<<NV / 16, 256>>>(0, 1, cw + 0, cb + 0);
    k_layer<<<NV / 16, 256>>>(1, 0, cw + 9, cb + 1);
    k_layer<<<NV / 16, 256>>>(0, 1, cw + 18, cb + 2);

    // final [T,3] projection
    k_final<<<dim3(TT / TTILE, NCHF), 512>>>(Wo, out);
}

// round 11
// speedup vs baseline: 1.0831x; 1.0179x over previous
#include <cuda_runtime.h>
#include <cuda_fp16.h>

// Problem constants (from reference)
#define NV 100000      // vertices
#define TT 128         // temporal depth
#define NE_MAX 1600000 // edges
#define MAXDEG 64      // padded segment capacity; deg ~ Poisson(16), P(>=64) ~ 2e-18/node
#define CVT_BLOCKS (NV * TT / 4 / 256)  // 12500

// ---------------- static device scratch (allocation-free) ----------------
__device__ __half g_hbuf[2][(size_t)NV * TT];     // ping-pong fp16 feature buffers (2 x 25.6MB)
__device__ int    g_deg[NV];
__device__ int    g_srcs[(size_t)NV * MAXDEG];    // padded segments; stores src*16 (uint4-row units)

// ---------------- helpers ----------------
__device__ __forceinline__ uint2 f4h2(float4 v) {
    __half2 a = __floats2half2_rn(v.x, v.y);
    __half2 b = __floats2half2_rn(v.z, v.w);
    uint2 r;
    r.x = *(unsigned*)&a;
    r.y = *(unsigned*)&b;
    return r;
}

// ---------------- tiny prologue: zero degrees + init out with bias ----------------
__global__ void k_zero(const float* __restrict__ bo, float* __restrict__ out) {
    int i = blockIdx.x * 256 + threadIdx.x;
    if (i < NV) g_deg[i] = 0;
    if (i < TT * 3) out[i] = __ldg(bo + (i % 3)); // out is 0xAA-poisoned
}

// ---------------- merged convert + CSR build (concurrent block roles) ----------------
// Build blocks (atomic-latency-bound, idle issue slots) and cvt blocks
// (bandwidth-bound) are independent; running them in ONE kernel lets the SMs
// overlap the two latency classes without stream forking (graph-capture safe).
// Build blocks come first so their long-latency atomic chains start immediately.
__global__ void k_cvt_build(const float4* __restrict__ x,
                            const int* __restrict__ src, const int* __restrict__ dst,
                            int E, int eb) {
    int b = blockIdx.x;
    if (b < eb) {
        // ---- CSR build: histogram atomic's return value IS the slot ----
        int i = (b * 256 + threadIdx.x) * 4;
        if (i + 4 <= E) {
            int d0 = dst[i], d1 = dst[i + 1], d2 = dst[i + 2], d3 = dst[i + 3];
            int s0 = src[i], s1 = src[i + 1], s2 = src[i + 2], s3 = src[i + 3];
            int r0 = atomicAdd(&g_deg[d0], 1);
            int r1 = atomicAdd(&g_deg[d1], 1);
            int r2 = atomicAdd(&g_deg[d2], 1);
            int r3 = atomicAdd(&g_deg[d3], 1);
            if (r0 < MAXDEG) g_srcs[d0 * MAXDEG + r0] = s0 * 16; // premultiplied uint4-row units
            if (r1 < MAXDEG) g_srcs[d1 * MAXDEG + r1] = s1 * 16;
            if (r2 < MAXDEG) g_srcs[d2 * MAXDEG + r2] = s2 * 16;
            if (r3 < MAXDEG) g_srcs[d3 * MAXDEG + r3] = s3 * 16;
        } else {
            for (; i < E; ++i) {
                int r = atomicAdd(&g_deg[dst[i]], 1);
                if (r < MAXDEG) g_srcs[dst[i] * MAXDEG + r] = src[i] * 16;
            }
        }
    } else {
        // ---- fp32 -> fp16 conversion ----
        int i = (b - eb) * 256 + threadIdx.x; // < NV*TT/4
        ((uint2*)g_hbuf[0])[i] = f4h2(x[i]);
    }
}

// ---------------- fused layer: mean-aggregate -> conv1d(K=9) -> relu ----------------
// conv and mean-agg commute exactly (linear; bias survives the mean).
// HALF-WARP per node: 16 lanes, each lane owns 8 consecutive t (one uint4 = 8 fp16).
// R8-proven body: scalar index loads, 4-edge fp16 tree, <=4 gathers in flight,
// 32 regs, occ 82%. int4 index loads (R10) and 8-edge trees (R4/R9) both
// regressed via register pressure — FROZEN.
__global__ void __launch_bounds__(256) k_layer(
    int in_sel, int out_sel,
    const float* __restrict__ cw, const float* __restrict__ cb)
{
    const uint4* __restrict__ xin = (const uint4*)g_hbuf[in_sel];
    uint4* __restrict__ xout = (uint4*)g_hbuf[out_sel];

    int lane  = threadIdx.x & 31;
    int slane = lane & 15;
    int n = blockIdx.x * 16 + ((threadIdx.x >> 5) << 1) + (lane >> 4);

    float w[9];
    #pragma unroll
    for (int k = 0; k < 9; k++) w[k] = __ldg(cw + k);
    float bias = __ldg(cb);

    unsigned rbase = (unsigned)n * 16u + (unsigned)slane;

    float acc[8];
    { // self loop (exact convert)
        uint4 p = xin[rbase];
        const __half2* h = (const __half2*)&p;
        #pragma unroll
        for (int q = 0; q < 4; q++) {
            float2 f = __half22float2(h[q]);
            acc[2 * q] = f.x; acc[2 * q + 1] = f.y;
        }
    }

    int deg = g_deg[n];
    if (deg > MAXDEG) deg = MAXDEG; // paranoia; statistically unreachable
    const int* __restrict__ seg = g_srcs + n * MAXDEG;
    float inv = 1.0f / (float)(deg + 1); // mean incl. self loop

    int j = 0;
    for (; j + 4 <= deg; j += 4) {
        unsigned s0 = (unsigned)seg[j];
        unsigned s1 = (unsigned)seg[j + 1];
        unsigned s2 = (unsigned)seg[j + 2];
        unsigned s3 = (unsigned)seg[j + 3];
        uint4 p0 = xin[s0 + slane];
        uint4 p1 = xin[s1 + slane];
        uint4 p2 = xin[s2 + slane];
        uint4 p3 = xin[s3 + slane];
        const __half2* h0 = (const __half2*)&p0;
        const __half2* h1 = (const __half2*)&p1;
        const __half2* h2 = (const __half2*)&p2;
        const __half2* h3 = (const __half2*)&p3;
        #pragma unroll
        for (int q = 0; q < 4; q++) {
            __half2 a01 = __hadd2(h0[q], h1[q]);      // fp16 tree: 2-level
            __half2 a23 = __hadd2(h2[q], h3[q]);
            float2 f = __half22float2(__hadd2(a01, a23));
            acc[2 * q] += f.x;
            acc[2 * q + 1] += f.y;
        }
    }
    for (; j < deg; ++j) { // tail <=3 edges: exact converts
        uint4 p = xin[(unsigned)seg[j] + slane];
        const __half2* h = (const __half2*)&p;
        #pragma unroll
        for (int q = 0; q < 4; q++) {
            float2 f = __half22float2(h[q]);
            acc[2 * q] += f.x; acc[2 * q + 1] += f.y;
        }
    }

    #pragma unroll
    for (int q = 0; q < 8; q++) acc[q] *= inv;

    // conv halo via width-16 shuffles
    float vv[16];
    #pragma unroll
    for (int q = 0; q < 8; q++) vv[4 + q] = acc[q];
    #pragma unroll
    for (int q = 0; q < 4; q++)
        vv[q] = __shfl_up_sync(0xffffffffu, acc[4 + q], 1, 16);
    #pragma unroll
    for (int q = 0; q < 4; q++)
        vv[12 + q] = __shfl_down_sync(0xffffffffu, acc[q], 1, 16);
    if (slane == 0)  { vv[0] = 0.f; vv[1] = 0.f; vv[2] = 0.f; vv[3] = 0.f; }
    if (slane == 15) { vv[12] = 0.f; vv[13] = 0.f; vv[14] = 0.f; vv[15] = 0.f; }

    float res[8];
    #pragma unroll
    for (int i = 0; i < 8; i++) {
        float o = bias;
        #pragma unroll
        for (int k = 0; k < 9; k++) o = fmaf(vv[i + k], w[k], o); // cross-correlation
        res[i] = fmaxf(o, 0.0f);
    }

    uint4 outp;
    unsigned* op = (unsigned*)&outp;
    #pragma unroll
    for (int q = 0; q < 4; q++) {
        __half2 hh = __floats2half2_rn(res[2 * q], res[2 * q + 1]);
        op[q] = *(unsigned*)&hh;
    }
    xout[rbase] = outp;
}

// ---------------- final projection ----------------
// x.reshape(T,N) on row-major [N,T] is a flat reinterpretation:
// out[t,c] = b[c] + sum_n hflat[t*N+n] * W[c*N+n]; both contiguous in n.
#define TTILE 8
#define NCHF 8
__global__ void __launch_bounds__(512) k_final(
    const float* __restrict__ W, float* __restrict__ out)
{
    const __half* __restrict__ h = g_hbuf[1];
    int t0 = blockIdx.x * TTILE;
    const int nper = NV / NCHF; // 12500
    int n0 = blockIdx.y * nper;

    float acc[TTILE][3];
    #pragma unroll
    for (int t = 0; t < TTILE; t++)
        #pragma unroll
        for (int c = 0; c < 3; c++) acc[t][c] = 0.f;

    for (int n = n0 + threadIdx.x; n < n0 + nper; n += 512) {
        float w0 = __ldg(W + n);
        float w1 = __ldg(W + NV + n);
        float w2 = __ldg(W + 2 * NV + n);
        #pragma unroll
        for (int t = 0; t < TTILE; t++) {
            float v = __half2float(h[(size_t)(t0 + t) * NV + n]);
            acc[t][0] = fmaf(v, w0, acc[t][0]);
            acc[t][1] = fmaf(v, w1, acc[t][1]);
            acc[t][2] = fmaf(v, w2, acc[t][2]);
        }
    }

    #pragma unroll
    for (int t = 0; t < TTILE; t++)
        #pragma unroll
        for (int c = 0; c < 3; c++)
            #pragma unroll
            for (int o = 16; o; o >>= 1)
                acc[t][c] += __shfl_down_sync(0xffffffffu, acc[t][c], o);

    __shared__ float sh[16][TTILE][3];
    int lane = threadIdx.x & 31, wid = threadIdx.x >> 5;
    if (lane == 0)
        #pragma unroll
        for (int t = 0; t < TTILE; t++)
            #pragma unroll
            for (int c = 0; c < 3; c++) sh[wid][t][c] = acc[t][c];
    __syncthreads();
    // 24 outputs per block: lanes 0..23 of warp 0
    if (wid == 0 && lane < TTILE * 3) {
        int t = lane / 3, c = lane % 3;
        float s = 0.f;
        #pragma unroll
        for (int wgi = 0; wgi < 16; wgi++) s += sh[wgi][t][c];
        atomicAdd(&out[(t0 + t) * 3 + c], s);
    }
}

// ---------------- launch ----------------
extern "C" void kernel_launch(void* const* d_in, const int* in_sizes, int n_in,
                              void* d_out, int out_size)
{
    const float* x  = (const float*)d_in[0];
    const int*   ei = (const int*)d_in[1];
    const float* cw = (const float*)d_in[2]; // [L,1,1,K]
    const float* cb = (const float*)d_in[3]; // [L,1]
    const float* Wo = (const float*)d_in[4]; // [3,N]
    const float* bo = (const float*)d_in[5]; // [3]
    float* out = (float*)d_out;

    int E = in_sizes[1] / 2;
    const int* src = ei;
    const int* dst = ei + E;

    // zero degrees + init out with bias (build depends on this)
    k_zero<<<(NV + 255) / 256, 256>>>(bo, out);

    // merged: CSR build blocks (first) run concurrently with fp32->fp16 cvt blocks
    int eb = (E / 4 + 255) / 256 + 1;
    k_cvt_build<<<eb + CVT_BLOCKS, 256>>>((const float4*)x, src, dst, E, eb);

    // 3 fused layers: agg -> conv -> relu, ping-pong fp16 buffers
    k_layer<<<NV / 16, 256>>>(0, 1, cw + 0, cb + 0);
    k_layer<<<NV / 16, 256>>>(1, 0, cw + 9, cb + 1);
    k_layer<<<NV / 16, 256>>>(0, 1, cw + 18, cb + 2);

    // final [T,3] projection
    k_final<<<dim3(TT / TTILE, NCHF), 512>>>(Wo, out);
}